// round 8
// baseline (speedup 1.0000x reference)
#include <cuda_runtime.h>
#include <mma.h>
#include <math.h>

using namespace nvcuda;

// Problem constants (B=1024, S=64, D=512, R=16, C=1000)
#define NB 1024
#define NS 64
#define ND 512
#define NR 16
#define NC 1000

// Scratch (allocation-free: __device__ globals)
__device__ float g_lrc[(size_t)NB * ND * NR];   // low_rank_cov (B, D, R)
__device__ float g_std[(size_t)NB * ND];        // diagonal_std (B, D)
__device__ float g_pre[(size_t)NB * NS * ND];   // pre_logits (B, S, D)

__device__ __forceinline__ float softplus_f(float x) {
    return fmaxf(x, 0.0f) + log1pf(expf(-fabsf(x)));
}

__device__ __forceinline__ float to_tf32(float x) {
    float r;
    asm("cvt.rna.tf32.f32 %0, %1;" : "=f"(r) : "f"(x));
    return r;
}

// ---------------------------------------------------------------------------
// NT GEMM on tensor cores (tf32 in, fp32 accumulate):
//   C[m,n] = sum_k A[m,k]*B[n,k]  (+ bias, epilogue)
// A: M x K row-major, B: N x K row-major, C: M x N row-major.
// Block tile 128x128, BK=16, 256 threads = 8 warps; each warp owns 64x32
// (warp_m = wid&1 -> 2 tiles of 64 in m; warp_n = wid>>1 -> 4 tiles of 32 in n)
// computed as 4x2 wmma fragments of 16x16 (k=8).
// Requires K % 16 == 0 and M % 128 == 0 (true: K=512, M in {1024, 65536}).
// N is bounds-checked (N=1000 case); B rows beyond N are zero-filled.
// EPI: 0 = +bias ; 1 = softplus(+bias)+1e-3 ; 2 = (+bias)*(1/1.5)
// ---------------------------------------------------------------------------
#define SKEW 20   // row stride in floats for smem tiles (80B, 16B-aligned)

template <int EPI>
__global__ __launch_bounds__(256) void tgemm_nt(
    const float* __restrict__ A, const float* __restrict__ Bm,
    const float* __restrict__ bias, float* __restrict__ C,
    int M, int N, int K)
{
    __shared__ __align__(16) float As[128 * SKEW];   // [row 0..127][k 0..15]
    __shared__ __align__(16) float Bs[128 * SKEW];   // [nrow 0..127][k 0..15]
    __shared__ __align__(16) float St[8][16 * SKEW]; // per-warp 16x16 staging

    const int tid  = threadIdx.x;
    const int wid  = tid >> 5;
    const int lane = tid & 31;
    const int warp_m = wid & 1;     // 0..1  (64-row slabs)
    const int warp_n = wid >> 1;    // 0..3  (32-col slabs)
    const int m0 = blockIdx.y * 128;
    const int n0 = blockIdx.x * 128;

    // Per-thread cooperative-load coordinates (2 float4 per tile per thread)
    int lrow[2], lc4[2];
    #pragma unroll
    for (int t = 0; t < 2; t++) {
        int idx = tid + t * 256;      // 0..511
        lrow[t] = idx >> 2;           // 0..127
        lc4[t]  = idx & 3;            // float4 slot within 16-k row
    }

    wmma::fragment<wmma::accumulator, 16, 16, 8, float> acc[4][2];
    #pragma unroll
    for (int i = 0; i < 4; i++)
        #pragma unroll
        for (int j = 0; j < 2; j++)
            wmma::fill_fragment(acc[i][j], 0.0f);

    float4 pa[2], pb[2];
    // Prefetch first K-tile
    #pragma unroll
    for (int t = 0; t < 2; t++) {
        pa[t] = *(const float4*)&A[(size_t)(m0 + lrow[t]) * K + lc4[t] * 4];
        int gn = n0 + lrow[t];
        pb[t] = (gn < N) ? *(const float4*)&Bm[(size_t)gn * K + lc4[t] * 4]
                         : make_float4(0.f, 0.f, 0.f, 0.f);
    }

    for (int kk = 0; kk < K; kk += 16) {
        // Commit prefetched tile to smem (tf32-rounded once here)
        #pragma unroll
        for (int t = 0; t < 2; t++) {
            float* ap = &As[lrow[t] * SKEW + lc4[t] * 4];
            ap[0] = to_tf32(pa[t].x); ap[1] = to_tf32(pa[t].y);
            ap[2] = to_tf32(pa[t].z); ap[3] = to_tf32(pa[t].w);
            float* bp = &Bs[lrow[t] * SKEW + lc4[t] * 4];
            bp[0] = to_tf32(pb[t].x); bp[1] = to_tf32(pb[t].y);
            bp[2] = to_tf32(pb[t].z); bp[3] = to_tf32(pb[t].w);
        }
        __syncthreads();

        // Kick off next tile's global loads (overlap with MMA below)
        const int kn = kk + 16;
        if (kn < K) {
            #pragma unroll
            for (int t = 0; t < 2; t++) {
                pa[t] = *(const float4*)&A[(size_t)(m0 + lrow[t]) * K + kn + lc4[t] * 4];
                int gn = n0 + lrow[t];
                pb[t] = (gn < N) ? *(const float4*)&Bm[(size_t)gn * K + kn + lc4[t] * 4]
                                 : make_float4(0.f, 0.f, 0.f, 0.f);
            }
        }

        #pragma unroll
        for (int ks = 0; ks < 16; ks += 8) {
            wmma::fragment<wmma::matrix_a, 16, 16, 8, wmma::precision::tf32,
                           wmma::row_major> af[4];
            wmma::fragment<wmma::matrix_b, 16, 16, 8, wmma::precision::tf32,
                           wmma::col_major> bf[2];
            #pragma unroll
            for (int i = 0; i < 4; i++)
                wmma::load_matrix_sync(af[i],
                    &As[(warp_m * 64 + i * 16) * SKEW + ks], SKEW);
            #pragma unroll
            for (int j = 0; j < 2; j++)
                wmma::load_matrix_sync(bf[j],
                    &Bs[(warp_n * 32 + j * 16) * SKEW + ks], SKEW);
            #pragma unroll
            for (int i = 0; i < 4; i++)
                #pragma unroll
                for (int j = 0; j < 2; j++)
                    wmma::mma_sync(acc[i][j], af[i], bf[j], acc[i][j]);
        }
        __syncthreads();
    }

    // Epilogue: stage each 16x16 fragment through per-warp smem, fuse bias+EPI.
    const int r  = lane >> 1;        // 0..15 row within fragment
    const int c0 = (lane & 1) * 8;   // 0 or 8: column start (8 cols per lane)
    #pragma unroll
    for (int i = 0; i < 4; i++) {
        #pragma unroll
        for (int j = 0; j < 2; j++) {
            wmma::store_matrix_sync(&St[wid][0], acc[i][j], SKEW,
                                    wmma::mem_row_major);
            __syncwarp();
            const int m = m0 + warp_m * 64 + i * 16 + r;
            const int nbase = n0 + warp_n * 32 + j * 16 + c0;
            #pragma unroll
            for (int c = 0; c < 8; c++) {
                int n = nbase + c;
                if (n < N) {
                    float v = St[wid][r * SKEW + c0 + c] + bias[n];
                    if (EPI == 1) v = softplus_f(v) + 1e-3f;
                    if (EPI == 2) v *= (1.0f / 1.5f);
                    C[(size_t)m * N + n] = v;
                }
            }
            __syncwarp();
        }
    }
}

// ---------------------------------------------------------------------------
// Sampling kernel: pre[b,s,d] = features[b,d]
//                              + sum_r lrc[b,d,r] * noise_lr[b,s,r]
//                              + std[b,d] * noise_diag[b,s,d]
// ---------------------------------------------------------------------------
__global__ __launch_bounds__(512) void sample_kernel(
    const float* __restrict__ features,
    const float* __restrict__ noise_diag,
    const float* __restrict__ noise_lr)
{
    const int b = blockIdx.x;
    const int d = threadIdx.x;   // 0..511

    __shared__ float nlr[NS * NR];  // noise_lr[b,:,:] (1024 floats)
    nlr[d]       = noise_lr[(size_t)b * NS * NR + d];
    nlr[d + 512] = noise_lr[(size_t)b * NS * NR + d + 512];
    __syncthreads();

    float lrc[NR];
    const float4* lp = (const float4*)&g_lrc[((size_t)b * ND + d) * NR];
    #pragma unroll
    for (int i = 0; i < 4; i++) {
        float4 v = lp[i];
        lrc[i * 4 + 0] = v.x; lrc[i * 4 + 1] = v.y;
        lrc[i * 4 + 2] = v.z; lrc[i * 4 + 3] = v.w;
    }

    const float feat = features[(size_t)b * ND + d];
    const float sd   = g_std[(size_t)b * ND + d];

    #pragma unroll 4
    for (int s = 0; s < NS; s++) {
        float acc = fmaf(sd, noise_diag[((size_t)b * NS + s) * ND + d], feat);
        #pragma unroll
        for (int r = 0; r < NR; r++)
            acc = fmaf(lrc[r], nlr[s * NR + r], acc);
        g_pre[((size_t)b * NS + s) * ND + d] = acc;
    }
}

// ---------------------------------------------------------------------------
// kernel_launch
// ---------------------------------------------------------------------------
extern "C" void kernel_launch(void* const* d_in, const int* in_sizes, int n_in,
                              void* d_out, int out_size)
{
    const float* features   = (const float*)d_in[0];
    const float* W_cov      = (const float*)d_in[1];
    const float* b_cov      = (const float*)d_in[2];
    const float* W_diag     = (const float*)d_in[3];
    const float* b_diag     = (const float*)d_in[4];
    const float* W_cls      = (const float*)d_in[5];
    const float* b_cls      = (const float*)d_in[6];
    const float* noise_diag = (const float*)d_in[7];
    const float* noise_lr   = (const float*)d_in[8];
    float* out = (float*)d_out;

    float *p_lrc, *p_std, *p_pre;
    cudaGetSymbolAddress((void**)&p_lrc, g_lrc);
    cudaGetSymbolAddress((void**)&p_std, g_std);
    cudaGetSymbolAddress((void**)&p_pre, g_pre);

    // 1) low_rank_cov: (1024 x 8192) = features (1024x512) @ W_cov^T
    {
        dim3 grid((ND * NR) / 128, NB / 128);
        tgemm_nt<0><<<grid, 256>>>(features, W_cov, b_cov, p_lrc,
                                   NB, ND * NR, ND);
    }
    // 2) diagonal_std: softplus(features @ W_diag^T + b_diag) + 1e-3
    {
        dim3 grid(ND / 128, NB / 128);
        tgemm_nt<1><<<grid, 256>>>(features, W_diag, b_diag, p_std,
                                   NB, ND, ND);
    }
    // 3) pre_logits
    sample_kernel<<<NB, ND>>>(features, noise_diag, noise_lr);

    // 4) logits: (65536 x 1000) = pre @ W_cls^T, (+bias)/1.5
    {
        dim3 grid((NC + 127) / 128, (NB * NS) / 128);
        tgemm_nt<2><<<grid, 256>>>(p_pre, W_cls, b_cls, out,
                                   NB * NS, NC, ND);
    }
}

// round 11
// speedup vs baseline: 1.2753x; 1.2753x over previous
#include <cuda_runtime.h>
#include <mma.h>
#include <math.h>

using namespace nvcuda;

// Problem constants (B=1024, S=64, D=512, R=16, C=1000)
#define NB 1024
#define NS 64
#define ND 512
#define NR 16
#define NC 1000

// Scratch (allocation-free: __device__ globals)
__device__ float g_lrc[(size_t)NB * ND * NR];    // low_rank_cov (B, D, R)
__device__ float g_std[(size_t)NB * ND];         // diagonal_std (B, D)
__device__ float g_pre[(size_t)NB * NS * ND];    // pre_logits, tf32-rounded
__device__ float g_feat[(size_t)NB * ND];        // features, tf32-rounded
__device__ float g_wcov[(size_t)ND * NR * ND];   // W_cov, tf32-rounded
__device__ float g_wdiag[(size_t)ND * ND];       // W_diag, tf32-rounded
__device__ float g_wcls[(size_t)NC * ND];        // W_cls, tf32-rounded

__device__ __forceinline__ float softplus_f(float x) {
    return fmaxf(x, 0.0f) + log1pf(expf(-fabsf(x)));
}

__device__ __forceinline__ float to_tf32(float x) {
    float r;
    asm("cvt.rna.tf32.f32 %0, %1;" : "=f"(r) : "f"(x));
    return r;
}

__device__ __forceinline__ void cp_async16(void* dst_smem, const void* src, int src_bytes) {
    unsigned d = (unsigned)__cvta_generic_to_shared(dst_smem);
    asm volatile("cp.async.cg.shared.global [%0], [%1], 16, %2;\n"
                 :: "r"(d), "l"(src), "r"(src_bytes));
}
__device__ __forceinline__ void cp_commit() {
    asm volatile("cp.async.commit_group;\n");
}
template <int W>
__device__ __forceinline__ void cp_wait() {
    asm volatile("cp.async.wait_group %0;\n" :: "n"(W));
}

// ---------------------------------------------------------------------------
// Elementwise tf32 rounding: out[i] = rna_tf32(in[i]). n % 4 == 0.
// ---------------------------------------------------------------------------
__global__ __launch_bounds__(256) void round_tf32_kernel(
    const float* __restrict__ in, float* __restrict__ out, int n)
{
    int i = (blockIdx.x * 256 + threadIdx.x) * 4;
    if (i < n) {
        float4 v = *(const float4*)(in + i);
        v.x = to_tf32(v.x); v.y = to_tf32(v.y);
        v.z = to_tf32(v.z); v.w = to_tf32(v.w);
        *(float4*)(out + i) = v;
    }
}

// ---------------------------------------------------------------------------
// NT GEMM on tensor cores (inputs already tf32-rounded, fp32 accumulate):
//   C[m,n] = sum_k A[m,k]*B[n,k]  (+ bias, epilogue)
// A: M x K row-major, B: N x K row-major, C: M x N row-major.
// Block tile 128x128, BK=16, 256 threads = 8 warps, each warp 64x32 (4x2
// fragments of 16x16 k=8). cp.async 2-stage smem pipeline, 2 CTAs/SM.
// Requires K % 16 == 0, M % 128 == 0. N bounds-checked (N=1000 case).
// EPI: 0 = +bias ; 1 = softplus(+bias)+1e-3 ; 2 = (+bias)*(1/1.5)
// ---------------------------------------------------------------------------
#define SKEW 20   // row stride in floats (80B, multiple of 16B)

template <int EPI>
__global__ __launch_bounds__(256, 2) void tgemm_nt(
    const float* __restrict__ A, const float* __restrict__ Bm,
    const float* __restrict__ bias, float* __restrict__ C,
    int M, int N, int K)
{
    __shared__ __align__(16) float As[2][128 * SKEW];
    __shared__ __align__(16) float Bs[2][128 * SKEW];
    // Epilogue staging aliases As[0] (safe after final barrier).

    const int tid  = threadIdx.x;
    const int wid  = tid >> 5;
    const int lane = tid & 31;
    const int warp_m = wid & 1;     // 0..1  (64-row slabs)
    const int warp_n = wid >> 1;    // 0..3  (32-col slabs)
    const int m0 = blockIdx.y * 128;
    const int n0 = blockIdx.x * 128;

    // Cooperative-load coords: 2 float4 per matrix per thread.
    int lrow[2], lc4[2];
    #pragma unroll
    for (int t = 0; t < 2; t++) {
        int idx = tid + t * 256;      // 0..511
        lrow[t] = idx >> 2;           // 0..127
        lc4[t]  = idx & 3;            // float4 slot within 16-k row
    }
    // Precompute B-row validity/clamped addresses (N=1000 edge).
    int bvalid[2], brow[2];
    #pragma unroll
    for (int t = 0; t < 2; t++) {
        int gn = n0 + lrow[t];
        bvalid[t] = (gn < N) ? 16 : 0;
        brow[t] = (gn < N) ? gn : (N - 1);
    }

    wmma::fragment<wmma::accumulator, 16, 16, 8, float> acc[4][2];
    #pragma unroll
    for (int i = 0; i < 4; i++)
        #pragma unroll
        for (int j = 0; j < 2; j++)
            wmma::fill_fragment(acc[i][j], 0.0f);

    const int nk = K / 16;

    // Stage-issue helper
    auto issue = [&](int stage, int kk) {
        #pragma unroll
        for (int t = 0; t < 2; t++) {
            cp_async16(&As[stage][lrow[t] * SKEW + lc4[t] * 4],
                       &A[(size_t)(m0 + lrow[t]) * K + kk + lc4[t] * 4], 16);
            cp_async16(&Bs[stage][lrow[t] * SKEW + lc4[t] * 4],
                       &Bm[(size_t)brow[t] * K + kk + lc4[t] * 4], bvalid[t]);
        }
        cp_commit();
    };

    issue(0, 0);

    for (int kt = 0; kt < nk; kt++) {
        if (kt + 1 < nk) {
            issue((kt + 1) & 1, (kt + 1) * 16);
            cp_wait<1>();
        } else {
            cp_wait<0>();
        }
        __syncthreads();

        const int st = kt & 1;
        #pragma unroll
        for (int ks = 0; ks < 16; ks += 8) {
            wmma::fragment<wmma::matrix_a, 16, 16, 8, wmma::precision::tf32,
                           wmma::row_major> af[4];
            wmma::fragment<wmma::matrix_b, 16, 16, 8, wmma::precision::tf32,
                           wmma::col_major> bf[2];
            #pragma unroll
            for (int i = 0; i < 4; i++)
                wmma::load_matrix_sync(af[i],
                    &As[st][(warp_m * 64 + i * 16) * SKEW + ks], SKEW);
            #pragma unroll
            for (int j = 0; j < 2; j++)
                wmma::load_matrix_sync(bf[j],
                    &Bs[st][(warp_n * 32 + j * 16) * SKEW + ks], SKEW);
            #pragma unroll
            for (int i = 0; i < 4; i++)
                #pragma unroll
                for (int j = 0; j < 2; j++)
                    wmma::mma_sync(acc[i][j], af[i], bf[j], acc[i][j]);
        }
        __syncthreads();
    }

    // Epilogue: stage fragments through smem (aliases As[0]), fuse bias+EPI.
    float* St = &As[0][0] + wid * (16 * SKEW);
    const int r  = lane >> 1;        // 0..15 row within fragment
    const int c0 = (lane & 1) * 8;   // 0 or 8
    #pragma unroll
    for (int i = 0; i < 4; i++) {
        #pragma unroll
        for (int j = 0; j < 2; j++) {
            wmma::store_matrix_sync(St, acc[i][j], SKEW, wmma::mem_row_major);
            __syncwarp();
            const int m = m0 + warp_m * 64 + i * 16 + r;
            const int nbase = n0 + warp_n * 32 + j * 16 + c0;
            #pragma unroll
            for (int c = 0; c < 8; c++) {
                int n = nbase + c;
                if (n < N) {
                    float v = St[r * SKEW + c0 + c] + bias[n];
                    if (EPI == 1) v = softplus_f(v) + 1e-3f;
                    if (EPI == 2) v *= (1.0f / 1.5f);
                    C[(size_t)m * N + n] = v;
                }
            }
            __syncwarp();
        }
    }
}

// ---------------------------------------------------------------------------
// Sampling kernel: pre[b,s,d] = tf32( features[b,d]
//                              + sum_r lrc[b,d,r] * noise_lr[b,s,r]
//                              + std[b,d] * noise_diag[b,s,d] )
// ---------------------------------------------------------------------------
__global__ __launch_bounds__(512) void sample_kernel(
    const float* __restrict__ features,
    const float* __restrict__ noise_diag,
    const float* __restrict__ noise_lr)
{
    const int b = blockIdx.x;
    const int d = threadIdx.x;   // 0..511

    __shared__ float nlr[NS * NR];  // noise_lr[b,:,:] (1024 floats)
    nlr[d]       = noise_lr[(size_t)b * NS * NR + d];
    nlr[d + 512] = noise_lr[(size_t)b * NS * NR + d + 512];
    __syncthreads();

    float lrc[NR];
    const float4* lp = (const float4*)&g_lrc[((size_t)b * ND + d) * NR];
    #pragma unroll
    for (int i = 0; i < 4; i++) {
        float4 v = lp[i];
        lrc[i * 4 + 0] = v.x; lrc[i * 4 + 1] = v.y;
        lrc[i * 4 + 2] = v.z; lrc[i * 4 + 3] = v.w;
    }

    const float feat = features[(size_t)b * ND + d];
    const float sd   = g_std[(size_t)b * ND + d];

    #pragma unroll 4
    for (int s = 0; s < NS; s++) {
        float acc = fmaf(sd, noise_diag[((size_t)b * NS + s) * ND + d], feat);
        #pragma unroll
        for (int r = 0; r < NR; r++)
            acc = fmaf(lrc[r], nlr[s * NR + r], acc);
        g_pre[((size_t)b * NS + s) * ND + d] = to_tf32(acc);
    }
}

// ---------------------------------------------------------------------------
// kernel_launch
// ---------------------------------------------------------------------------
extern "C" void kernel_launch(void* const* d_in, const int* in_sizes, int n_in,
                              void* d_out, int out_size)
{
    const float* features   = (const float*)d_in[0];
    const float* W_cov      = (const float*)d_in[1];
    const float* b_cov      = (const float*)d_in[2];
    const float* W_diag     = (const float*)d_in[3];
    const float* b_diag     = (const float*)d_in[4];
    const float* W_cls      = (const float*)d_in[5];
    const float* b_cls      = (const float*)d_in[6];
    const float* noise_diag = (const float*)d_in[7];
    const float* noise_lr   = (const float*)d_in[8];
    float* out = (float*)d_out;

    float *p_lrc, *p_std, *p_pre, *p_feat, *p_wcov, *p_wdiag, *p_wcls;
    cudaGetSymbolAddress((void**)&p_lrc,  g_lrc);
    cudaGetSymbolAddress((void**)&p_std,  g_std);
    cudaGetSymbolAddress((void**)&p_pre,  g_pre);
    cudaGetSymbolAddress((void**)&p_feat, g_feat);
    cudaGetSymbolAddress((void**)&p_wcov, g_wcov);
    cudaGetSymbolAddress((void**)&p_wdiag,g_wdiag);
    cudaGetSymbolAddress((void**)&p_wcls, g_wcls);

    // 0) Round GEMM inputs to tf32 once (hoists cvt out of GEMM hot loops).
    {
        int n;
        n = NB * ND;
        round_tf32_kernel<<<(n / 4 + 255) / 256, 256>>>(features, p_feat, n);
        n = ND * NR * ND;
        round_tf32_kernel<<<(n / 4 + 255) / 256, 256>>>(W_cov, p_wcov, n);
        n = ND * ND;
        round_tf32_kernel<<<(n / 4 + 255) / 256, 256>>>(W_diag, p_wdiag, n);
        n = NC * ND;
        round_tf32_kernel<<<(n / 4 + 255) / 256, 256>>>(W_cls, p_wcls, n);
    }

    // 1) low_rank_cov: (1024 x 8192) = feat @ W_cov^T
    {
        dim3 grid((ND * NR) / 128, NB / 128);
        tgemm_nt<0><<<grid, 256>>>(p_feat, p_wcov, b_cov, p_lrc,
                                   NB, ND * NR, ND);
    }
    // 2) diagonal_std: softplus(feat @ W_diag^T + b_diag) + 1e-3
    {
        dim3 grid(ND / 128, NB / 128);
        tgemm_nt<1><<<grid, 256>>>(p_feat, p_wdiag, b_diag, p_std,
                                   NB, ND, ND);
    }
    // 3) pre_logits (tf32-rounded at write)
    sample_kernel<<<NB, ND>>>(features, noise_diag, noise_lr);

    // 4) logits: (65536 x 1000) = pre @ W_cls^T, (+bias)/1.5
    {
        dim3 grid((NC + 127) / 128, (NB * NS) / 128);
        tgemm_nt<2><<<grid, 256>>>(p_pre, p_wcls, b_cls, out,
                                   NB * NS, NC, ND);
    }
}

// round 16
// speedup vs baseline: 1.2807x; 1.0042x over previous
#include <cuda_runtime.h>
#include <mma.h>
#include <math.h>

using namespace nvcuda;

// Problem constants (B=1024, S=64, D=512, R=16, C=1000)
#define NB 1024
#define NS 64
#define ND 512
#define NR 16
#define NC 1000

// Scratch (allocation-free: __device__ globals)
__device__ float g_lrc[(size_t)NB * ND * NR];    // low_rank_cov (B, D, R)
__device__ float g_std[(size_t)NB * ND];         // diagonal_std (B, D)
__device__ float g_pre[(size_t)NB * NS * ND];    // pre_logits, tf32-rounded
__device__ float g_feat[(size_t)NB * ND];        // features, tf32-rounded
__device__ float g_wcov[(size_t)ND * NR * ND];   // W_cov, tf32-rounded
__device__ float g_wdiag[(size_t)ND * ND];       // W_diag, tf32-rounded
__device__ float g_wcls[(size_t)NC * ND];        // W_cls, tf32-rounded

__device__ __forceinline__ float softplus_f(float x) {
    return fmaxf(x, 0.0f) + log1pf(expf(-fabsf(x)));
}

__device__ __forceinline__ float to_tf32(float x) {
    float r;
    asm("cvt.rna.tf32.f32 %0, %1;" : "=f"(r) : "f"(x));
    return r;
}

__device__ __forceinline__ void cp_async16(void* dst_smem, const void* src, int src_bytes) {
    unsigned d = (unsigned)__cvta_generic_to_shared(dst_smem);
    asm volatile("cp.async.cg.shared.global [%0], [%1], 16, %2;\n"
                 :: "r"(d), "l"(src), "r"(src_bytes));
}
__device__ __forceinline__ void cp_commit() {
    asm volatile("cp.async.commit_group;\n");
}
template <int W>
__device__ __forceinline__ void cp_wait() {
    asm volatile("cp.async.wait_group %0;\n" :: "n"(W));
}

// ---------------------------------------------------------------------------
// Elementwise tf32 rounding: out[i] = rna_tf32(in[i]). n % 4 == 0.
// ---------------------------------------------------------------------------
__global__ __launch_bounds__(256) void round_tf32_kernel(
    const float* __restrict__ in, float* __restrict__ out, int n)
{
    int i = (blockIdx.x * 256 + threadIdx.x) * 4;
    if (i < n) {
        float4 v = *(const float4*)(in + i);
        v.x = to_tf32(v.x); v.y = to_tf32(v.y);
        v.z = to_tf32(v.z); v.w = to_tf32(v.w);
        *(float4*)(out + i) = v;
    }
}

// ---------------------------------------------------------------------------
// NT GEMM on tensor cores (inputs already tf32-rounded, fp32 accumulate):
//   C[m,n] = sum_k A[m,k]*B[n,k]  (+ bias, epilogue)
// A: M x K row-major, B: N x K row-major, C: M x N row-major.
// Block tile 128x128, BK=16, 256 threads = 8 warps, each warp 64x32 (4x2
// fragments of 16x16 k=8). 3-stage cp.async smem pipeline, ONE barrier per
// K-tile, 2 CTAs/SM. Dynamic smem (61,440 B).
// Requires K % 16 == 0, M % 128 == 0. N bounds-checked (N=1000 case).
// EPI: 0 = +bias ; 1 = softplus(+bias)+1e-3 ; 2 = (+bias)*(1/1.5)
// ---------------------------------------------------------------------------
#define SKEW 20                        // row stride in floats (80B, multiple of 16B)
#define TSTRIDE (128 * SKEW)           // floats per tile (A or B, one stage)
#define TBYTES (TSTRIDE * 4)           // 10,240 B
#define NSTAGE 3
#define GSMEM (2 * NSTAGE * TBYTES)    // 61,440 B

template <int EPI>
__global__ __launch_bounds__(256, 2) void tgemm_nt(
    const float* __restrict__ A, const float* __restrict__ Bm,
    const float* __restrict__ bias, float* __restrict__ C,
    int M, int N, int K)
{
    extern __shared__ __align__(16) float smem[];
    // Layout: A stages [0..3*TSTRIDE), B stages [3*TSTRIDE..6*TSTRIDE).
    float* As = smem;
    float* Bs = smem + NSTAGE * TSTRIDE;

    const int tid  = threadIdx.x;
    const int wid  = tid >> 5;
    const int lane = tid & 31;
    const int warp_m = wid & 1;     // 0..1  (64-row slabs)
    const int warp_n = wid >> 1;    // 0..3  (32-col slabs)
    const int m0 = blockIdx.y * 128;
    const int n0 = blockIdx.x * 128;

    // Cooperative-load coords: 2 float4 per matrix per thread.
    int lrow[2], lc4[2];
    #pragma unroll
    for (int t = 0; t < 2; t++) {
        int idx = tid + t * 256;      // 0..511
        lrow[t] = idx >> 2;           // 0..127
        lc4[t]  = idx & 3;            // float4 slot within 16-k row
    }
    // Precompute B-row validity/clamped addresses (N=1000 edge).
    int bvalid[2], brow[2];
    #pragma unroll
    for (int t = 0; t < 2; t++) {
        int gn = n0 + lrow[t];
        bvalid[t] = (gn < N) ? 16 : 0;
        brow[t] = (gn < N) ? gn : (N - 1);
    }

    wmma::fragment<wmma::accumulator, 16, 16, 8, float> acc[4][2];
    #pragma unroll
    for (int i = 0; i < 4; i++)
        #pragma unroll
        for (int j = 0; j < 2; j++)
            wmma::fill_fragment(acc[i][j], 0.0f);

    const int nk = K / 16;

    auto issue = [&](int stage, int kk) {
        float* as = As + stage * TSTRIDE;
        float* bs = Bs + stage * TSTRIDE;
        #pragma unroll
        for (int t = 0; t < 2; t++) {
            cp_async16(&as[lrow[t] * SKEW + lc4[t] * 4],
                       &A[(size_t)(m0 + lrow[t]) * K + kk + lc4[t] * 4], 16);
            cp_async16(&bs[lrow[t] * SKEW + lc4[t] * 4],
                       &Bm[(size_t)brow[t] * K + kk + lc4[t] * 4], bvalid[t]);
        }
        cp_commit();
    };

    // Prefill two stages.
    issue(0, 0);
    if (nk > 1) issue(1, 16);

    for (int kt = 0; kt < nk; kt++) {
        // Ensure chunk kt's group has landed (kt+1 may stay in flight).
        if (kt + 1 < nk) cp_wait<1>(); else cp_wait<0>();
        __syncthreads();   // all threads see stage kt; all finished compute kt-1

        if (kt + 2 < nk) issue((kt + 2) % NSTAGE, (kt + 2) * 16);

        const float* as = As + (kt % NSTAGE) * TSTRIDE;
        const float* bs = Bs + (kt % NSTAGE) * TSTRIDE;
        #pragma unroll
        for (int ks = 0; ks < 16; ks += 8) {
            wmma::fragment<wmma::matrix_a, 16, 16, 8, wmma::precision::tf32,
                           wmma::row_major> af[4];
            wmma::fragment<wmma::matrix_b, 16, 16, 8, wmma::precision::tf32,
                           wmma::col_major> bf[2];
            #pragma unroll
            for (int i = 0; i < 4; i++)
                wmma::load_matrix_sync(af[i],
                    &as[(warp_m * 64 + i * 16) * SKEW + ks], SKEW);
            #pragma unroll
            for (int j = 0; j < 2; j++)
                wmma::load_matrix_sync(bf[j],
                    &bs[(warp_n * 32 + j * 16) * SKEW + ks], SKEW);
            #pragma unroll
            for (int i = 0; i < 4; i++)
                #pragma unroll
                for (int j = 0; j < 2; j++)
                    wmma::mma_sync(acc[i][j], af[i], bf[j], acc[i][j]);
        }
    }

    __syncthreads();   // all compute done before epilogue reuses stage-0 smem

    // Epilogue: stage fragments through smem (aliases A stage 0), fuse bias+EPI.
    float* St = As + wid * (16 * SKEW);
    const int r  = lane >> 1;        // 0..15 row within fragment
    const int c0 = (lane & 1) * 8;   // 0 or 8
    #pragma unroll
    for (int i = 0; i < 4; i++) {
        #pragma unroll
        for (int j = 0; j < 2; j++) {
            wmma::store_matrix_sync(St, acc[i][j], SKEW, wmma::mem_row_major);
            __syncwarp();
            const int m = m0 + warp_m * 64 + i * 16 + r;
            const int nbase = n0 + warp_n * 32 + j * 16 + c0;
            #pragma unroll
            for (int c = 0; c < 8; c++) {
                int n = nbase + c;
                if (n < N) {
                    float v = St[r * SKEW + c0 + c] + bias[n];
                    if (EPI == 1) v = softplus_f(v) + 1e-3f;
                    if (EPI == 2) v *= (1.0f / 1.5f);
                    C[(size_t)m * N + n] = v;
                }
            }
            __syncwarp();
        }
    }
}

// ---------------------------------------------------------------------------
// Sampling kernel: pre[b,s,d] = tf32( features[b,d]
//                              + sum_r lrc[b,d,r] * noise_lr[b,s,r]
//                              + std[b,d] * noise_diag[b,s,d] )
// ---------------------------------------------------------------------------
__global__ __launch_bounds__(512) void sample_kernel(
    const float* __restrict__ features,
    const float* __restrict__ noise_diag,
    const float* __restrict__ noise_lr)
{
    const int b = blockIdx.x;
    const int d = threadIdx.x;   // 0..511

    __shared__ float nlr[NS * NR];  // noise_lr[b,:,:] (1024 floats)
    nlr[d]       = noise_lr[(size_t)b * NS * NR + d];
    nlr[d + 512] = noise_lr[(size_t)b * NS * NR + d + 512];
    __syncthreads();

    float lrc[NR];
    const float4* lp = (const float4*)&g_lrc[((size_t)b * ND + d) * NR];
    #pragma unroll
    for (int i = 0; i < 4; i++) {
        float4 v = lp[i];
        lrc[i * 4 + 0] = v.x; lrc[i * 4 + 1] = v.y;
        lrc[i * 4 + 2] = v.z; lrc[i * 4 + 3] = v.w;
    }

    const float feat = features[(size_t)b * ND + d];
    const float sd   = g_std[(size_t)b * ND + d];

    #pragma unroll 4
    for (int s = 0; s < NS; s++) {
        float acc = fmaf(sd, noise_diag[((size_t)b * NS + s) * ND + d], feat);
        #pragma unroll
        for (int r = 0; r < NR; r++)
            acc = fmaf(lrc[r], nlr[s * NR + r], acc);
        g_pre[((size_t)b * NS + s) * ND + d] = to_tf32(acc);
    }
}

// ---------------------------------------------------------------------------
// kernel_launch
// ---------------------------------------------------------------------------
extern "C" void kernel_launch(void* const* d_in, const int* in_sizes, int n_in,
                              void* d_out, int out_size)
{
    const float* features   = (const float*)d_in[0];
    const float* W_cov      = (const float*)d_in[1];
    const float* b_cov      = (const float*)d_in[2];
    const float* W_diag     = (const float*)d_in[3];
    const float* b_diag     = (const float*)d_in[4];
    const float* W_cls      = (const float*)d_in[5];
    const float* b_cls      = (const float*)d_in[6];
    const float* noise_diag = (const float*)d_in[7];
    const float* noise_lr   = (const float*)d_in[8];
    float* out = (float*)d_out;

    float *p_lrc, *p_std, *p_pre, *p_feat, *p_wcov, *p_wdiag, *p_wcls;
    cudaGetSymbolAddress((void**)&p_lrc,  g_lrc);
    cudaGetSymbolAddress((void**)&p_std,  g_std);
    cudaGetSymbolAddress((void**)&p_pre,  g_pre);
    cudaGetSymbolAddress((void**)&p_feat, g_feat);
    cudaGetSymbolAddress((void**)&p_wcov, g_wcov);
    cudaGetSymbolAddress((void**)&p_wdiag,g_wdiag);
    cudaGetSymbolAddress((void**)&p_wcls, g_wcls);

    // Allow >48KB dynamic smem (idempotent).
    cudaFuncSetAttribute(tgemm_nt<0>, cudaFuncAttributeMaxDynamicSharedMemorySize, GSMEM);
    cudaFuncSetAttribute(tgemm_nt<1>, cudaFuncAttributeMaxDynamicSharedMemorySize, GSMEM);
    cudaFuncSetAttribute(tgemm_nt<2>, cudaFuncAttributeMaxDynamicSharedMemorySize, GSMEM);

    // 0) Round GEMM inputs to tf32 once (hoists cvt out of GEMM hot loops).
    {
        int n;
        n = NB * ND;
        round_tf32_kernel<<<(n / 4 + 255) / 256, 256>>>(features, p_feat, n);
        n = ND * NR * ND;
        round_tf32_kernel<<<(n / 4 + 255) / 256, 256>>>(W_cov, p_wcov, n);
        n = ND * ND;
        round_tf32_kernel<<<(n / 4 + 255) / 256, 256>>>(W_diag, p_wdiag, n);
        n = NC * ND;
        round_tf32_kernel<<<(n / 4 + 255) / 256, 256>>>(W_cls, p_wcls, n);
    }

    // 1) low_rank_cov: (1024 x 8192) = feat @ W_cov^T
    {
        dim3 grid((ND * NR) / 128, NB / 128);
        tgemm_nt<0><<<grid, 256, GSMEM>>>(p_feat, p_wcov, b_cov, p_lrc,
                                          NB, ND * NR, ND);
    }
    // 2) diagonal_std: softplus(feat @ W_diag^T + b_diag) + 1e-3
    {
        dim3 grid(ND / 128, NB / 128);
        tgemm_nt<1><<<grid, 256, GSMEM>>>(p_feat, p_wdiag, b_diag, p_std,
                                          NB, ND, ND);
    }
    // 3) pre_logits (tf32-rounded at write)
    sample_kernel<<<NB, ND>>>(features, noise_diag, noise_lr);

    // 4) logits: (65536 x 1000) = pre @ W_cls^T, (+bias)/1.5
    {
        dim3 grid((NC + 127) / 128, (NB * NS) / 128);
        tgemm_nt<2><<<grid, 256, GSMEM>>>(p_pre, p_wcls, b_cls, out,
                                          NB * NS, NC, ND);
    }
}

// round 17
// speedup vs baseline: 3.0222x; 2.3599x over previous
#include <cuda_runtime.h>
#include <cuda_fp16.h>
#include <mma.h>
#include <math.h>

using namespace nvcuda;

// Problem constants (B=1024, S=64, D=512, R=16, C=1000)
#define NB 1024
#define NS 64
#define ND 512
#define NR 16
#define NC 1000

// Scratch (allocation-free: __device__ globals)
__device__ float  g_lrc[(size_t)NB * ND * NR];    // low_rank_cov (B, D, R)
__device__ float  g_std[(size_t)NB * ND];         // diagonal_std (B, D)
__device__ __half g_pre_h[(size_t)NB * NS * ND];  // pre_logits, fp16
__device__ __half g_feat_h[(size_t)NB * ND];      // features, fp16
__device__ __half g_wcov_h[(size_t)ND * NR * ND]; // W_cov, fp16
__device__ __half g_wdiag_h[(size_t)ND * ND];     // W_diag, fp16
__device__ __half g_wcls_h[(size_t)NC * ND];      // W_cls, fp16

__device__ __forceinline__ float softplus_f(float x) {
    return fmaxf(x, 0.0f) + log1pf(expf(-fabsf(x)));
}

__device__ __forceinline__ void cp_async16(void* dst_smem, const void* src, int src_bytes) {
    unsigned d = (unsigned)__cvta_generic_to_shared(dst_smem);
    asm volatile("cp.async.cg.shared.global [%0], [%1], 16, %2;\n"
                 :: "r"(d), "l"(src), "r"(src_bytes));
}
__device__ __forceinline__ void cp_commit() {
    asm volatile("cp.async.commit_group;\n");
}
template <int W>
__device__ __forceinline__ void cp_wait() {
    asm volatile("cp.async.wait_group %0;\n" :: "n"(W));
}

// ---------------------------------------------------------------------------
// Elementwise fp32 -> fp16 conversion (RN). n % 8 == 0.
// ---------------------------------------------------------------------------
__global__ __launch_bounds__(256) void f2h_kernel(
    const float* __restrict__ in, __half* __restrict__ out, int n)
{
    int i = (blockIdx.x * 256 + threadIdx.x) * 8;
    if (i < n) {
        float4 a = *(const float4*)(in + i);
        float4 b = *(const float4*)(in + i + 4);
        __half2 h0 = __floats2half2_rn(a.x, a.y);
        __half2 h1 = __floats2half2_rn(a.z, a.w);
        __half2 h2 = __floats2half2_rn(b.x, b.y);
        __half2 h3 = __floats2half2_rn(b.z, b.w);
        uint4 u;
        u.x = *(unsigned*)&h0; u.y = *(unsigned*)&h1;
        u.z = *(unsigned*)&h2; u.w = *(unsigned*)&h3;
        *(uint4*)(out + i) = u;
    }
}

// ---------------------------------------------------------------------------
// NT GEMM on tensor cores (fp16 in, fp32 accumulate):
//   C[m,n] = sum_k A[m,k]*B[n,k]  (+ bias, epilogue)
// A: M x K row-major fp16, B: N x K row-major fp16, C: M x N row-major fp32.
// Block tile 128x128, BK=32, 256 threads = 8 warps, each warp 64x32 (4x2
// fragments of 16x16 k=16). 3-stage cp.async smem pipeline, ONE barrier per
// K-tile, 2 CTAs/SM. Dynamic smem (61,440 B).
// Requires K % 32 == 0, M % 128 == 0. N bounds-checked (N=1000 case).
// EPI: 0 = +bias ; 1 = softplus(+bias)+1e-3 ; 2 = (+bias)*(1/1.5)
// ---------------------------------------------------------------------------
#define SKEWH 40                        // halfs per smem row (80 B, mult of 16B)
#define TSTRIDE_H (128 * SKEWH)         // halfs per tile-stage (one matrix)
#define TBYTES_H (TSTRIDE_H * 2)        // 10,240 B
#define NSTAGE 3
#define GSMEM (2 * NSTAGE * TBYTES_H)   // 61,440 B
#define SKEWS 20                        // floats per row for epilogue staging

template <int EPI>
__global__ __launch_bounds__(256, 2) void hgemm_nt(
    const __half* __restrict__ A, const __half* __restrict__ Bm,
    const float* __restrict__ bias, float* __restrict__ C,
    int M, int N, int K)
{
    extern __shared__ __align__(16) __half smem[];
    __half* As = smem;                       // 3 stages
    __half* Bs = smem + NSTAGE * TSTRIDE_H;  // 3 stages

    const int tid  = threadIdx.x;
    const int wid  = tid >> 5;
    const int lane = tid & 31;
    const int warp_m = wid & 1;     // 0..1  (64-row slabs)
    const int warp_n = wid >> 1;    // 0..3  (32-col slabs)
    const int m0 = blockIdx.y * 128;
    const int n0 = blockIdx.x * 128;

    // Cooperative-load coords: 32 halfs/row = 4 granules of 16B.
    // 128 rows x 4 granules = 512 per matrix; 256 threads -> 2 per matrix.
    int lrow[2], lc16[2];
    #pragma unroll
    for (int t = 0; t < 2; t++) {
        int g = tid + t * 256;        // 0..511
        lrow[t] = g >> 2;             // 0..127
        lc16[t] = g & 3;              // granule within 32-half row
    }
    int bvalid[2], brow[2];
    #pragma unroll
    for (int t = 0; t < 2; t++) {
        int gn = n0 + lrow[t];
        bvalid[t] = (gn < N) ? 16 : 0;
        brow[t] = (gn < N) ? gn : (N - 1);
    }

    wmma::fragment<wmma::accumulator, 16, 16, 16, float> acc[4][2];
    #pragma unroll
    for (int i = 0; i < 4; i++)
        #pragma unroll
        for (int j = 0; j < 2; j++)
            wmma::fill_fragment(acc[i][j], 0.0f);

    const int nk = K / 32;

    auto issue = [&](int stage, int kk) {
        __half* as = As + stage * TSTRIDE_H;
        __half* bs = Bs + stage * TSTRIDE_H;
        #pragma unroll
        for (int t = 0; t < 2; t++) {
            cp_async16(&as[lrow[t] * SKEWH + lc16[t] * 8],
                       &A[(size_t)(m0 + lrow[t]) * K + kk + lc16[t] * 8], 16);
            cp_async16(&bs[lrow[t] * SKEWH + lc16[t] * 8],
                       &Bm[(size_t)brow[t] * K + kk + lc16[t] * 8], bvalid[t]);
        }
        cp_commit();
    };

    issue(0, 0);
    if (nk > 1) issue(1, 32);

    for (int kt = 0; kt < nk; kt++) {
        if (kt + 1 < nk) cp_wait<1>(); else cp_wait<0>();
        __syncthreads();   // stage kt visible; compute kt-1 done block-wide

        if (kt + 2 < nk) issue((kt + 2) % NSTAGE, (kt + 2) * 32);

        const __half* as = As + (kt % NSTAGE) * TSTRIDE_H;
        const __half* bs = Bs + (kt % NSTAGE) * TSTRIDE_H;
        #pragma unroll
        for (int ks = 0; ks < 32; ks += 16) {
            wmma::fragment<wmma::matrix_a, 16, 16, 16, __half,
                           wmma::row_major> af[4];
            wmma::fragment<wmma::matrix_b, 16, 16, 16, __half,
                           wmma::col_major> bf[2];
            #pragma unroll
            for (int i = 0; i < 4; i++)
                wmma::load_matrix_sync(af[i],
                    &as[(warp_m * 64 + i * 16) * SKEWH + ks], SKEWH);
            #pragma unroll
            for (int j = 0; j < 2; j++)
                wmma::load_matrix_sync(bf[j],
                    &bs[(warp_n * 32 + j * 16) * SKEWH + ks], SKEWH);
            #pragma unroll
            for (int i = 0; i < 4; i++)
                #pragma unroll
                for (int j = 0; j < 2; j++)
                    wmma::mma_sync(acc[i][j], af[i], bf[j], acc[i][j]);
        }
    }

    __syncthreads();   // compute done before epilogue reuses smem

    // Epilogue: stage fragments through smem (reuse A-stage region as float).
    float* St = reinterpret_cast<float*>(As) + wid * (16 * SKEWS);
    const int r  = lane >> 1;
    const int c0 = (lane & 1) * 8;
    #pragma unroll
    for (int i = 0; i < 4; i++) {
        #pragma unroll
        for (int j = 0; j < 2; j++) {
            wmma::store_matrix_sync(St, acc[i][j], SKEWS, wmma::mem_row_major);
            __syncwarp();
            const int m = m0 + warp_m * 64 + i * 16 + r;
            const int nbase = n0 + warp_n * 32 + j * 16 + c0;
            #pragma unroll
            for (int c = 0; c < 8; c++) {
                int n = nbase + c;
                if (n < N) {
                    float v = St[r * SKEWS + c0 + c] + bias[n];
                    if (EPI == 1) v = softplus_f(v) + 1e-3f;
                    if (EPI == 2) v *= (1.0f / 1.5f);
                    C[(size_t)m * N + n] = v;
                }
            }
            __syncwarp();
        }
    }
}

// ---------------------------------------------------------------------------
// Sampling kernel: pre[b,s,d] = fp16( features[b,d]
//                              + sum_r lrc[b,d,r] * noise_lr[b,s,r]
//                              + std[b,d] * noise_diag[b,s,d] )
// ---------------------------------------------------------------------------
__global__ __launch_bounds__(512) void sample_kernel(
    const float* __restrict__ features,
    const float* __restrict__ noise_diag,
    const float* __restrict__ noise_lr)
{
    const int b = blockIdx.x;
    const int d = threadIdx.x;   // 0..511

    __shared__ float nlr[NS * NR];  // noise_lr[b,:,:] (1024 floats)
    nlr[d]       = noise_lr[(size_t)b * NS * NR + d];
    nlr[d + 512] = noise_lr[(size_t)b * NS * NR + d + 512];
    __syncthreads();

    float lrc[NR];
    const float4* lp = (const float4*)&g_lrc[((size_t)b * ND + d) * NR];
    #pragma unroll
    for (int i = 0; i < 4; i++) {
        float4 v = lp[i];
        lrc[i * 4 + 0] = v.x; lrc[i * 4 + 1] = v.y;
        lrc[i * 4 + 2] = v.z; lrc[i * 4 + 3] = v.w;
    }

    const float feat = features[(size_t)b * ND + d];
    const float sd   = g_std[(size_t)b * ND + d];

    #pragma unroll 4
    for (int s = 0; s < NS; s++) {
        float acc = fmaf(sd, noise_diag[((size_t)b * NS + s) * ND + d], feat);
        #pragma unroll
        for (int r = 0; r < NR; r++)
            acc = fmaf(lrc[r], nlr[s * NR + r], acc);
        g_pre_h[((size_t)b * NS + s) * ND + d] = __float2half_rn(acc);
    }
}

// ---------------------------------------------------------------------------
// kernel_launch
// ---------------------------------------------------------------------------
extern "C" void kernel_launch(void* const* d_in, const int* in_sizes, int n_in,
                              void* d_out, int out_size)
{
    const float* features   = (const float*)d_in[0];
    const float* W_cov      = (const float*)d_in[1];
    const float* b_cov      = (const float*)d_in[2];
    const float* W_diag     = (const float*)d_in[3];
    const float* b_diag     = (const float*)d_in[4];
    const float* W_cls      = (const float*)d_in[5];
    const float* b_cls      = (const float*)d_in[6];
    const float* noise_diag = (const float*)d_in[7];
    const float* noise_lr   = (const float*)d_in[8];
    float* out = (float*)d_out;

    float *p_lrc, *p_std;
    __half *p_pre, *p_feat, *p_wcov, *p_wdiag, *p_wcls;
    cudaGetSymbolAddress((void**)&p_lrc,  g_lrc);
    cudaGetSymbolAddress((void**)&p_std,  g_std);
    cudaGetSymbolAddress((void**)&p_pre,  g_pre_h);
    cudaGetSymbolAddress((void**)&p_feat, g_feat_h);
    cudaGetSymbolAddress((void**)&p_wcov, g_wcov_h);
    cudaGetSymbolAddress((void**)&p_wdiag,g_wdiag_h);
    cudaGetSymbolAddress((void**)&p_wcls, g_wcls_h);

    cudaFuncSetAttribute(hgemm_nt<0>, cudaFuncAttributeMaxDynamicSharedMemorySize, GSMEM);
    cudaFuncSetAttribute(hgemm_nt<1>, cudaFuncAttributeMaxDynamicSharedMemorySize, GSMEM);
    cudaFuncSetAttribute(hgemm_nt<2>, cudaFuncAttributeMaxDynamicSharedMemorySize, GSMEM);

    // 0) Convert GEMM inputs to fp16 once.
    {
        int n;
        n = NB * ND;
        f2h_kernel<<<(n / 8 + 255) / 256, 256>>>(features, p_feat, n);
        n = ND * NR * ND;
        f2h_kernel<<<(n / 8 + 255) / 256, 256>>>(W_cov, p_wcov, n);
        n = ND * ND;
        f2h_kernel<<<(n / 8 + 255) / 256, 256>>>(W_diag, p_wdiag, n);
        n = NC * ND;
        f2h_kernel<<<(n / 8 + 255) / 256, 256>>>(W_cls, p_wcls, n);
    }

    // 1) low_rank_cov: (1024 x 8192) = feat @ W_cov^T  (fp16 in, fp32 out)
    {
        dim3 grid((ND * NR) / 128, NB / 128);
        hgemm_nt<0><<<grid, 256, GSMEM>>>(p_feat, p_wcov, b_cov, p_lrc,
                                          NB, ND * NR, ND);
    }
    // 2) diagonal_std: softplus(feat @ W_diag^T + b_diag) + 1e-3
    {
        dim3 grid(ND / 128, NB / 128);
        hgemm_nt<1><<<grid, 256, GSMEM>>>(p_feat, p_wdiag, b_diag, p_std,
                                          NB, ND, ND);
    }
    // 3) pre_logits (fp16 at write, fp32 compute inside)
    sample_kernel<<<NB, ND>>>(features, noise_diag, noise_lr);

    // 4) logits: (65536 x 1000) = pre @ W_cls^T, (+bias)/1.5
    {
        dim3 grid((NC + 127) / 128, (NB * NS) / 128);
        hgemm_nt<2><<<grid, 256, GSMEM>>>(p_pre, p_wcls, b_cls, out,
                                          NB * NS, NC, ND);
    }
}